// round 11
// baseline (speedup 1.0000x reference)
#include <cuda_runtime.h>
#include <cstdint>

#define N_MAX 100000
#define E_MAX 600000
#define HF 128

// ---------------- scratch (static __device__ — no allocation) ----------------
__device__ __align__(16) float d_bufA[N_MAX * HF];
__device__ __align__(16) float d_bufB[N_MAX * HF];
__device__ int   d_cnt[N_MAX];
__device__ int   d_incl[N_MAX];
__device__ int   d_rs[N_MAX + 1];
__device__ int   d_cursor[N_MAX];
__device__ int   d_csr[E_MAX];
__device__ float d_dinv[N_MAX];
__device__ float d_sc[N_MAX];     // dinv/deg
__device__ int   d_bsum[256];

__device__ __forceinline__ uint32_t smem_u32(const void* p) {
    uint32_t a;
    asm("{ .reg .u64 t; cvta.to.shared.u64 t, %1; cvt.u32.u64 %0, t; }" : "=r"(a) : "l"(p));
    return a;
}
__device__ __forceinline__ void cpa16(uint32_t dst, const void* src, int ssz) {
    asm volatile("cp.async.ca.shared.global [%0], [%1], 16, %2;"
                 :: "r"(dst), "l"(src), "r"(ssz) : "memory");
}
__device__ __forceinline__ void cpa_commit() {
    asm volatile("cp.async.commit_group;" ::: "memory");
}
template <int N>
__device__ __forceinline__ void cpa_wait() {
    asm volatile("cp.async.wait_group %0;" :: "n"(N) : "memory");
}

// ---------------- preprocessing: CSR-by-target + degree terms ----------------
__global__ void k_hist(const int* __restrict__ col, int e, int n) {
    int i = blockIdx.x * blockDim.x + threadIdx.x;
    if (i < e) {
        int c = col[i];
        if (c >= 0 && c < n) atomicAdd(&d_cnt[c], 1);
    }
}

__global__ void k_scan1(int n) {
    __shared__ int s[1024];
    int t = threadIdx.x;
    int i = blockIdx.x * 1024 + t;
    s[t] = (i < n) ? d_cnt[i] : 0;
    __syncthreads();
    for (int off = 1; off < 1024; off <<= 1) {
        int a = 0;
        if (t >= off) a = s[t - off];
        __syncthreads();
        s[t] += a;
        __syncthreads();
    }
    if (i < n) d_incl[i] = s[t];
    if (t == 1023) d_bsum[blockIdx.x] = s[1023];
}

// scan3 with the cross-block prefix (old scan2) computed inline per block:
// each 256-thread block spans exactly one 1024-chunk index q = blockIdx>>2.
__global__ void k_scan3(int n, int nb) {
    __shared__ int sb[256];
    __shared__ int sbase;
    int tid = threadIdx.x;
    if (tid < nb) sb[tid] = d_bsum[tid];
    __syncthreads();
    if (tid == 0) {
        int q = blockIdx.x >> 2;
        int run = 0;
        for (int b = 0; b < q; ++b) run += sb[b];
        sbase = run;
    }
    __syncthreads();

    int i = blockIdx.x * 256 + tid;
    if (i >= n) return;
    int gi = d_incl[i] + sbase;
    int c  = d_cnt[i];
    d_cnt[i] = 0;                        // re-zero for next graph replay
    int st = gi - c;
    d_rs[i] = st;
    d_cursor[i] = st;
    if (i == n - 1) d_rs[n] = gi;
    float deg = (float)(c + 1);          // degree incl. self-loop
    float di = rsqrtf(deg);
    d_dinv[i] = di;
    d_sc[i]   = di / deg;
}

__global__ void k_scatter(const int* __restrict__ ei, int e, int n) {
    int i = blockIdx.x * blockDim.x + threadIdx.x;
    if (i >= e) return;
    int c = ei[e + i];  // col (target)
    int r = ei[i];      // row (source)
    if (c < 0 || c >= n || r < 0 || r >= n) return;
    int pos = atomicAdd(&d_cursor[c], 1);
    d_csr[pos] = r;
}

// ---------------- fp32 GEMM with cp.async pipeline ----------------
// dst = rowscale * ((A * colscale?) @ W^T + bias), optional relu.  Optionally fuses
// the final linear (H->40) + log_softmax into the epilogue (fuse_lin2).
// 128x128 tile, 256 threads, 8x8 microtile. W loaded ONCE transposed with swizzle
// f(k) = (k>>2) ^ ((k&3)<<3)  ->  fill stores AND compute loads bank-conflict-free.
// A in 32-k chunks, double-buffered via cp.async.
// smem: Bs 64KB @0; As[2][128][36] @65536.
#define OFF_AS  65536
#define APITCH  36
#define ASTAGE  (128 * APITCH * 4)          // 18432 B
#define GEMM_SMEM (OFF_AS + 2 * ASTAGE)     // 102400 B
// fused-lin2 epilogue layout (all regions dead by then):
#define HB_PITCH 133
#define OFF_WS2  68096
#define OFF_EXM  90112
#define OFF_EXS  91136

__global__ void __launch_bounds__(256, 2) k_gemm(
    const float* __restrict__ Aext,       // nullptr -> d_bufA
    const float* __restrict__ W,          // weight [128][128] row-major
    const float* __restrict__ bias,
    const float* __restrict__ colscale,   // nullptr or [128]: folded into W fill
    int use_dinv, int relu,
    int fuse_lin2,
    const float* __restrict__ Wl2,        // [40][128] (fused mode)
    const float* __restrict__ bl2,        // [40]
    float* __restrict__ out,              // [n][40]  (fused mode)
    int n)
{
    extern __shared__ __align__(16) char sm[];
    uint32_t smb = smem_u32(sm);
    float* Bs = (float*)sm;
    int tid = threadIdx.x;
    int tx = tid & 15, ty = tid >> 4;
    int row0 = blockIdx.x * 128;
    const float* A = Aext ? Aext : d_bufA;

    // ---- prefetch A chunk 0 ----
    {
        #pragma unroll
        for (int t = 0; t < 4; ++t) {
            int idx = tid + t * 256;            // 0..1023
            int r = idx >> 3, c4 = idx & 7;
            int gr = row0 + r;
            uint32_t dst = smb + OFF_AS + (uint32_t)(r * 144 + c4 * 16);
            cpa16(dst, A + (size_t)gr * 128 + c4 * 4, gr < n ? 16 : 0);
        }
        cpa_commit();
    }

    // ---- load full W transposed, swizzle f(k)=(k>>2)^((k&3)<<3): conflict-free ----
    {
        const float4* W4 = (const float4*)W;
        const float4* cs4 = (const float4*)colscale;
        #pragma unroll
        for (int it = 0; it < 16; ++it) {
            int idx = tid + it * 256;           // 0..4095
            int j = idx >> 5, kq = idx & 31;
            float4 v = W4[j * 32 + kq];
            if (colscale) {
                float4 c = cs4[kq];
                v.x *= c.x; v.y *= c.y; v.z *= c.z; v.w *= c.w;
            }
            // k = 4*kq + i  ->  f = kq ^ (i<<3)
            Bs[(kq * 4 + 0) * 128 + (j ^ kq)]          = v.x;
            Bs[(kq * 4 + 1) * 128 + (j ^ kq ^ 8)]      = v.y;
            Bs[(kq * 4 + 2) * 128 + (j ^ kq ^ 16)]     = v.z;
            Bs[(kq * 4 + 3) * 128 + (j ^ kq ^ 24)]     = v.w;
        }
    }

    float acc[8][8];
    #pragma unroll
    for (int i = 0; i < 8; i++)
        #pragma unroll
        for (int j = 0; j < 8; j++) acc[i][j] = 0.f;

    for (int kc = 0; kc < 4; ++kc) {
        if (kc < 3) {
            #pragma unroll
            for (int t = 0; t < 4; ++t) {
                int idx = tid + t * 256;
                int r = idx >> 3, c4 = idx & 7;
                int gr = row0 + r;
                uint32_t dst = smb + OFF_AS + (uint32_t)(((kc + 1) & 1) * ASTAGE)
                             + (uint32_t)(r * 144 + c4 * 16);
                cpa16(dst, A + (size_t)gr * 128 + (kc + 1) * 32 + c4 * 4, gr < n ? 16 : 0);
            }
            cpa_commit();
            cpa_wait<1>();
        } else {
            cpa_wait<0>();
        }
        __syncthreads();

        const float* As = (const float*)(sm + OFF_AS + (kc & 1) * ASTAGE);
        #pragma unroll 4
        for (int kl = 0; kl < 32; ++kl) {
            int k = kc * 32 + kl;
            int f = (k >> 2) ^ ((k & 3) << 3);
            float a[8], b[8];
            #pragma unroll
            for (int ii = 0; ii < 8; ii++) a[ii] = As[(ty + ii * 16) * APITCH + kl];
            #pragma unroll
            for (int jj = 0; jj < 8; jj++) b[jj] = Bs[k * 128 + ((tx + jj * 16) ^ f)];
            #pragma unroll
            for (int ii = 0; ii < 8; ii++)
                #pragma unroll
                for (int jj = 0; jj < 8; jj++)
                    acc[ii][jj] += a[ii] * b[jj];
        }
        if (kc < 3) __syncthreads();
    }

    if (!fuse_lin2) {
        // ---- plain epilogue: bias, rowscale, optional relu -> d_bufB ----
        #pragma unroll
        for (int ii = 0; ii < 8; ii++) {
            int gr = row0 + ty + ii * 16;
            if (gr >= n) continue;
            float rs = use_dinv ? d_dinv[gr] : 1.f;
            #pragma unroll
            for (int jj = 0; jj < 8; jj++) {
                int jc = tx + jj * 16;
                float v = (acc[ii][jj] + bias[jc]) * rs;
                if (relu) v = fmaxf(v, 0.f);
                d_bufB[(size_t)gr * 128 + jc] = v;
            }
        }
        return;
    }

    // ---- fused lin2 + log_softmax epilogue (lin1 semantics: h = relu(acc+bias)) ----
    __syncthreads();                        // all smem regions now dead; reuse
    float* hb  = (float*)sm;                // h tile [128][HB_PITCH]
    float* Ws2 = (float*)(sm + OFF_WS2);    // Ws2[k*40 + c] = Wl2[c*128 + k]
    float* exm = (float*)(sm + OFF_EXM);    // [2][128]
    float* exs = (float*)(sm + OFF_EXS);    // [2][128]

    #pragma unroll
    for (int ii = 0; ii < 8; ii++) {
        int r = ty + ii * 16;
        #pragma unroll
        for (int jj = 0; jj < 8; jj++) {
            int jc = tx + jj * 16;
            hb[r * HB_PITCH + jc] = fmaxf(acc[ii][jj] + bias[jc], 0.f);
        }
    }
    for (int idx = tid; idx < 5120; idx += 256) {
        int c = idx >> 7, k = idx & 127;
        Ws2[k * 40 + c] = Wl2[idx];
    }
    __syncthreads();

    int row = tid & 127;
    int half = tid >> 7;
    int c0 = half * 20;

    float acc2[20];
    #pragma unroll
    for (int c = 0; c < 20; ++c) acc2[c] = bl2[c0 + c];

    const float* hr = hb + row * HB_PITCH;
    #pragma unroll 4
    for (int k = 0; k < 128; ++k) {
        float a = hr[k];
        const float2* w2 = (const float2*)(Ws2 + k * 40 + c0);
        #pragma unroll
        for (int q = 0; q < 10; ++q) {
            float2 w = w2[q];
            acc2[2 * q]     += a * w.x;
            acc2[2 * q + 1] += a * w.y;
        }
    }

    float m = acc2[0];
    #pragma unroll
    for (int c = 1; c < 20; ++c) m = fmaxf(m, acc2[c]);
    exm[half * 128 + row] = m;
    __syncthreads();
    m = fmaxf(exm[row], exm[128 + row]);

    float s = 0.f;
    #pragma unroll
    for (int c = 0; c < 20; ++c) s += __expf(acc2[c] - m);
    exs[half * 128 + row] = s;
    __syncthreads();
    s = exs[row] + exs[128 + row];
    float ls = m + __logf(s);

    int grow = row0 + row;
    if (grow < n) {
        float4* o4 = (float4*)(out + (size_t)grow * 40 + c0);
        #pragma unroll
        for (int q = 0; q < 5; ++q) {
            float4 o;
            o.x = acc2[q * 4 + 0] - ls;
            o.y = acc2[q * 4 + 1] - ls;
            o.z = acc2[q * 4 + 2] - ls;
            o.w = acc2[q * 4 + 3] - ls;
            o4[q] = o;
        }
    }
}

// ---------------- aggregation: bufA[c] = relu(sc[c]*(bufB[c]+sum bufB[src]) + bc) --------
__global__ void k_agg(const float* __restrict__ bc, int n)
{
    int w = (blockIdx.x * blockDim.x + threadIdx.x) >> 5;
    int lane = threadIdx.x & 31;
    if (w >= n) return;
    const float4* g = (const float4*)d_bufB;
    float4 s = g[w * 32 + lane];   // self-loop term
    int beg = d_rs[w], end = d_rs[w + 1];
    for (int e = beg; e < end; ++e) {
        int src = d_csr[e];
        float4 v = g[src * 32 + lane];
        s.x += v.x; s.y += v.y; s.z += v.z; s.w += v.w;
    }
    float kf = d_sc[w];
    float bx = bc[lane * 4 + 0], by = bc[lane * 4 + 1];
    float bz = bc[lane * 4 + 2], bw = bc[lane * 4 + 3];
    float4 o;
    o.x = fmaxf(kf * s.x + bx, 0.f);
    o.y = fmaxf(kf * s.y + by, 0.f);
    o.z = fmaxf(kf * s.z + bz, 0.f);
    o.w = fmaxf(kf * s.w + bw, 0.f);
    ((float4*)d_bufA)[w * 32 + lane] = o;
}

// ---------------- launch ----------------
extern "C" void kernel_launch(void* const* d_in, const int* in_sizes, int n_in,
                              void* d_out, int out_size)
{
    const float* x    = (const float*)d_in[0];
    const int*   ei   = (const int*)d_in[1];     // int32 (JAX x64 disabled)
    const float* imp  = (const float*)d_in[2];
    const float* W1   = (const float*)d_in[3];
    const float* bl1  = (const float*)d_in[4];
    const float* bc1  = (const float*)d_in[5];
    const float* W2   = (const float*)d_in[6];
    const float* bl2  = (const float*)d_in[7];
    const float* bc2  = (const float*)d_in[8];
    const float* W3   = (const float*)d_in[9];
    const float* bl3  = (const float*)d_in[10];
    const float* bc3  = (const float*)d_in[11];
    const float* Wl1  = (const float*)d_in[12];
    const float* bli1 = (const float*)d_in[13];
    const float* Wl2  = (const float*)d_in[14];
    const float* bli2 = (const float*)d_in[15];
    int n = in_sizes[0] / HF;
    int e = in_sizes[1] / 2;
    float* out = (float*)d_out;

    cudaFuncSetAttribute(k_gemm, cudaFuncAttributeMaxDynamicSharedMemorySize, GEMM_SMEM);

    // preprocessing: CSR build + degree scaling (4 launches)
    k_hist   <<<(e + 255) / 256, 256>>>(ei + e, e, n);
    int nb = (n + 1023) / 1024;
    k_scan1  <<<nb, 1024>>>(n);
    k_scan3  <<<(n + 255) / 256, 256>>>(n, nb);
    k_scatter<<<(e + 255) / 256, 256>>>(ei, e, n);

    int gblocks = (n + 127) / 128;
    int ablocks = (n + 7) / 8;

    // conv1: A = x, imp folded into Bs fill; dinv rowscale in epilogue -> bufB
    k_gemm<<<gblocks, 256, GEMM_SMEM>>>(x, W1, bl1, imp, 1, 0,
                                        0, nullptr, nullptr, nullptr, n);
    k_agg <<<ablocks, 256>>>(bc1, n);
    // conv2
    k_gemm<<<gblocks, 256, GEMM_SMEM>>>(nullptr, W2, bl2, nullptr, 1, 0,
                                        0, nullptr, nullptr, nullptr, n);
    k_agg <<<ablocks, 256>>>(bc2, n);
    // conv3
    k_gemm<<<gblocks, 256, GEMM_SMEM>>>(nullptr, W3, bl3, nullptr, 1, 0,
                                        0, nullptr, nullptr, nullptr, n);
    k_agg <<<ablocks, 256>>>(bc3, n);
    // lin1 + relu, fused lin2 + log_softmax -> out
    k_gemm<<<gblocks, 256, GEMM_SMEM>>>(nullptr, Wl1, bli1, nullptr, 0, 1,
                                        1, Wl2, bli2, out, n);
}

// round 12
// speedup vs baseline: 1.1808x; 1.1808x over previous
#include <cuda_runtime.h>
#include <cstdint>

#define N_MAX 100000
#define E_MAX 600000
#define HF 128

// ---------------- scratch (static __device__ — no allocation) ----------------
__device__ __align__(16) float d_bufA[N_MAX * HF];
__device__ __align__(16) float d_bufB[N_MAX * HF];
__device__ int   d_cnt[N_MAX];
__device__ int   d_incl[N_MAX];
__device__ int   d_rs[N_MAX + 1];
__device__ int   d_cursor[N_MAX];
__device__ int   d_csr[E_MAX];
__device__ float d_dinv[N_MAX];
__device__ float d_sc[N_MAX];     // dinv/deg
__device__ int   d_bsum[256];
__device__ int   d_bpref[256];
// k-major W images: d_wimgT[l][k*128 + j] = W_l[j][k] (* imp[k] for l==0)
__device__ __align__(16) float d_wimgT[4][16384];

// ---------------- preprocessing: CSR-by-target + degree terms ----------------
__global__ void k_hist(const int* __restrict__ col, int e, int n) {
    int i = blockIdx.x * blockDim.x + threadIdx.x;
    if (i < e) {
        int c = col[i];
        if (c >= 0 && c < n) atomicAdd(&d_cnt[c], 1);
    }
}

__global__ void k_scan1(int n) {
    __shared__ int s[1024];
    int t = threadIdx.x;
    int i = blockIdx.x * 1024 + t;
    s[t] = (i < n) ? d_cnt[i] : 0;
    __syncthreads();
    for (int off = 1; off < 1024; off <<= 1) {
        int a = 0;
        if (t >= off) a = s[t - off];
        __syncthreads();
        s[t] += a;
        __syncthreads();
    }
    if (i < n) d_incl[i] = s[t];
    if (t == 1023) d_bsum[blockIdx.x] = s[1023];
}

__global__ void k_scan2(int nb) {   // single warp, shfl scan with carry
    int lane = threadIdx.x;
    int carry = 0;
    for (int base = 0; base < nb; base += 32) {
        int i = base + lane;
        int own = (i < nb) ? d_bsum[i] : 0;
        int v = own;
        #pragma unroll
        for (int o = 1; o < 32; o <<= 1) {
            int t = __shfl_up_sync(0xffffffffu, v, o);
            if (lane >= o) v += t;
        }
        if (i < nb) d_bpref[i] = carry + v - own;   // exclusive
        carry += __shfl_sync(0xffffffffu, v, 31);
    }
}

__global__ void k_scan3(int n) {
    int i = blockIdx.x * blockDim.x + threadIdx.x;
    if (i >= n) return;
    int gi = d_incl[i] + d_bpref[i >> 10];
    int c  = d_cnt[i];
    d_cnt[i] = 0;                        // re-zero for next graph replay
    int st = gi - c;
    d_rs[i] = st;
    d_cursor[i] = st;
    if (i == n - 1) d_rs[n] = gi;
    float deg = (float)(c + 1);          // degree incl. self-loop
    float di = rsqrtf(deg);
    d_dinv[i] = di;
    d_sc[i]   = di / deg;
}

__global__ void k_scatter(const int* __restrict__ ei, int e, int n) {
    int i = blockIdx.x * blockDim.x + threadIdx.x;
    if (i >= e) return;
    int c = ei[e + i];  // col (target)
    int r = ei[i];      // row (source)
    if (c < 0 || c >= n || r < 0 || r >= n) return;
    int pos = atomicAdd(&d_cursor[c], 1);
    d_csr[pos] = r;
}

// ---------------- W prep: k-major transpose (imp folded into layer 0) ----------------
__global__ void __launch_bounds__(256) k_prepw(
    const float* __restrict__ Wa, const float* __restrict__ Wb,
    const float* __restrict__ Wc, const float* __restrict__ Wd,
    const float* __restrict__ imp)
{
    int l = blockIdx.x;
    const float* W = (l == 0) ? Wa : (l == 1) ? Wb : (l == 2) ? Wc : Wd;
    for (int idx = threadIdx.x; idx < 16384; idx += 256) {
        int k = idx >> 7, j = idx & 127;
        float v = W[j * 128 + k];
        if (l == 0) v *= imp[k];
        d_wimgT[l][idx] = v;
    }
}

// ---------------- fp32 GEMM, vectorized smem operands ----------------
// dst = rowscale * (A @ W^T + bias), optional relu; optional fused lin2+log_softmax.
// 128x128 tile, 256 threads, 8x8 microtile (rows {4ty+i, +64}, cols {4tx+j, +64}).
// Bs: k-major, 16B-chunk XOR swizzle (chunk ^ (k&31)): fill & loads conflict-free.
// As: k-major [2][32][128], register-staged LDG prefetch + transpose scatter.
// Inner loop: 2 broadcast LDS.128 (a) + 2 swizzled LDS.128 (b) + 64 FFMA.
#define OFF_AS   65536
#define ASTAGE4  1024                       // float4s per stage
#define GEMM_SMEM (65536 + 32768)           // 98304 B
// fused-lin2 epilogue layout (reuses all smem):
#define HB_PITCH 133
#define OFF_WS2  68096                      // 128*133*4
#define OFF_EXM  88576                      // +5120*4
#define OFF_EXS  89600

__global__ void __launch_bounds__(256, 2) k_gemm(
    const float* __restrict__ Aext,       // nullptr -> d_bufA
    const float* __restrict__ bias,
    int wsel,                             // which d_wimgT image
    int use_dinv, int relu,
    int fuse_lin2,
    const float* __restrict__ Wl2,        // [40][128] (fused mode)
    const float* __restrict__ bl2,        // [40]
    float* __restrict__ out,              // [n][40]  (fused mode)
    int n)
{
    extern __shared__ __align__(16) char sm[];
    float4* Bs4 = (float4*)sm;
    float*  Asf = (float*)(sm + OFF_AS);
    int tid = threadIdx.x;
    int tx = tid & 15, ty = tid >> 4;
    int row0 = blockIdx.x * 128;
    const float* A = Aext ? Aext : d_bufA;
    const float4* S4 = (const float4*)A;
    const float* wT = d_wimgT[wsel];      // device-side symbol reference

    int lr = tid >> 1, lh = tid & 1;      // loader: row, k-half
    int lgr = row0 + lr;

    // ---- Bs fill: coalesced copy of wT, 16B-chunk swizzle (conflict-free) ----
    {
        const float4* wT4 = (const float4*)wT;
        #pragma unroll
        for (int it = 0; it < 16; ++it) {
            int idx = tid + it * 256;           // 0..4095
            int k = idx >> 5, j4 = idx & 31;
            Bs4[k * 32 + (j4 ^ (k & 31))] = wT4[idx];
        }
    }

    // ---- A chunk 0 -> regs -> stage 0 (transpose scatter) ----
    float4 nxt0, nxt1, nxt2, nxt3;
    nxt0 = nxt1 = nxt2 = nxt3 = make_float4(0.f, 0.f, 0.f, 0.f);
    if (lgr < n) {
        size_t b = (size_t)lgr * 32 + lh * 4;
        nxt0 = S4[b + 0]; nxt1 = S4[b + 1]; nxt2 = S4[b + 2]; nxt3 = S4[b + 3];
    }
    {
        int kb = lh * 16;
        Asf[(kb + 0) * 128 + lr] = nxt0.x;  Asf[(kb + 1) * 128 + lr] = nxt0.y;
        Asf[(kb + 2) * 128 + lr] = nxt0.z;  Asf[(kb + 3) * 128 + lr] = nxt0.w;
        Asf[(kb + 4) * 128 + lr] = nxt1.x;  Asf[(kb + 5) * 128 + lr] = nxt1.y;
        Asf[(kb + 6) * 128 + lr] = nxt1.z;  Asf[(kb + 7) * 128 + lr] = nxt1.w;
        Asf[(kb + 8) * 128 + lr] = nxt2.x;  Asf[(kb + 9) * 128 + lr] = nxt2.y;
        Asf[(kb +10) * 128 + lr] = nxt2.z;  Asf[(kb +11) * 128 + lr] = nxt2.w;
        Asf[(kb +12) * 128 + lr] = nxt3.x;  Asf[(kb +13) * 128 + lr] = nxt3.y;
        Asf[(kb +14) * 128 + lr] = nxt3.z;  Asf[(kb +15) * 128 + lr] = nxt3.w;
    }
    __syncthreads();

    float acc[8][8];
    #pragma unroll
    for (int i = 0; i < 8; i++)
        #pragma unroll
        for (int j = 0; j < 8; j++) acc[i][j] = 0.f;

    for (int kc = 0; kc < 4; ++kc) {
        if (kc < 3) {                     // prefetch next chunk to registers
            nxt0 = nxt1 = nxt2 = nxt3 = make_float4(0.f, 0.f, 0.f, 0.f);
            if (lgr < n) {
                size_t b = (size_t)lgr * 32 + (kc + 1) * 8 + lh * 4;
                nxt0 = S4[b + 0]; nxt1 = S4[b + 1]; nxt2 = S4[b + 2]; nxt3 = S4[b + 3];
            }
        }

        const float4* A4s = (const float4*)(Asf + (kc & 1) * (ASTAGE4 * 4));
        int kbase = kc * 32;
        #pragma unroll 8
        for (int kl = 0; kl < 32; ++kl) {
            float4 a0 = A4s[kl * 32 + ty];
            float4 a1 = A4s[kl * 32 + ty + 16];
            float4 b0 = Bs4[(kbase + kl) * 32 + (tx ^ kl)];
            float4 b1 = Bs4[(kbase + kl) * 32 + ((tx + 16) ^ kl)];
            float av[8] = {a0.x, a0.y, a0.z, a0.w, a1.x, a1.y, a1.z, a1.w};
            float bv[8] = {b0.x, b0.y, b0.z, b0.w, b1.x, b1.y, b1.z, b1.w};
            #pragma unroll
            for (int ii = 0; ii < 8; ii++)
                #pragma unroll
                for (int jj = 0; jj < 8; jj++)
                    acc[ii][jj] += av[ii] * bv[jj];
        }

        if (kc < 3) {
            float* dst = Asf + ((kc + 1) & 1) * (ASTAGE4 * 4);
            int kb = lh * 16;
            dst[(kb + 0) * 128 + lr] = nxt0.x;  dst[(kb + 1) * 128 + lr] = nxt0.y;
            dst[(kb + 2) * 128 + lr] = nxt0.z;  dst[(kb + 3) * 128 + lr] = nxt0.w;
            dst[(kb + 4) * 128 + lr] = nxt1.x;  dst[(kb + 5) * 128 + lr] = nxt1.y;
            dst[(kb + 6) * 128 + lr] = nxt1.z;  dst[(kb + 7) * 128 + lr] = nxt1.w;
            dst[(kb + 8) * 128 + lr] = nxt2.x;  dst[(kb + 9) * 128 + lr] = nxt2.y;
            dst[(kb +10) * 128 + lr] = nxt2.z;  dst[(kb +11) * 128 + lr] = nxt2.w;
            dst[(kb +12) * 128 + lr] = nxt3.x;  dst[(kb +13) * 128 + lr] = nxt3.y;
            dst[(kb +14) * 128 + lr] = nxt3.z;  dst[(kb +15) * 128 + lr] = nxt3.w;
            __syncthreads();
        }
    }

    if (!fuse_lin2) {
        // ---- plain epilogue -> d_bufB (float4 stores) ----
        #pragma unroll
        for (int ii = 0; ii < 8; ii++) {
            int gr = row0 + ty * 4 + (ii & 3) + (ii >> 2) * 64;
            if (gr >= n) continue;
            float rs = use_dinv ? d_dinv[gr] : 1.f;
            #pragma unroll
            for (int g = 0; g < 2; ++g) {
                int c0 = tx * 4 + g * 64;
                float4 o;
                o.x = (acc[ii][g * 4 + 0] + bias[c0 + 0]) * rs;
                o.y = (acc[ii][g * 4 + 1] + bias[c0 + 1]) * rs;
                o.z = (acc[ii][g * 4 + 2] + bias[c0 + 2]) * rs;
                o.w = (acc[ii][g * 4 + 3] + bias[c0 + 3]) * rs;
                if (relu) {
                    o.x = fmaxf(o.x, 0.f); o.y = fmaxf(o.y, 0.f);
                    o.z = fmaxf(o.z, 0.f); o.w = fmaxf(o.w, 0.f);
                }
                *(float4*)(d_bufB + (size_t)gr * 128 + c0) = o;
            }
        }
        return;
    }

    // ---- fused lin2 + log_softmax epilogue (h = relu(acc+bias)) ----
    __syncthreads();                        // all smem dead; reuse
    float* hb  = (float*)sm;                // [128][HB_PITCH]
    float* Ws2 = (float*)(sm + OFF_WS2);    // Ws2[k*40 + c] = Wl2[c*128 + k]
    float* exm = (float*)(sm + OFF_EXM);
    float* exs = (float*)(sm + OFF_EXS);

    #pragma unroll
    for (int ii = 0; ii < 8; ii++) {
        int r = ty * 4 + (ii & 3) + (ii >> 2) * 64;
        #pragma unroll
        for (int g = 0; g < 2; ++g) {
            int c0 = tx * 4 + g * 64;
            hb[r * HB_PITCH + c0 + 0] = fmaxf(acc[ii][g * 4 + 0] + bias[c0 + 0], 0.f);
            hb[r * HB_PITCH + c0 + 1] = fmaxf(acc[ii][g * 4 + 1] + bias[c0 + 1], 0.f);
            hb[r * HB_PITCH + c0 + 2] = fmaxf(acc[ii][g * 4 + 2] + bias[c0 + 2], 0.f);
            hb[r * HB_PITCH + c0 + 3] = fmaxf(acc[ii][g * 4 + 3] + bias[c0 + 3], 0.f);
        }
    }
    for (int idx = tid; idx < 5120; idx += 256) {
        int c = idx >> 7, k = idx & 127;
        Ws2[k * 40 + c] = Wl2[idx];
    }
    __syncthreads();

    int row = tid & 127;
    int half = tid >> 7;
    int c0 = half * 20;

    float acc2[20];
    #pragma unroll
    for (int c = 0; c < 20; ++c) acc2[c] = bl2[c0 + c];

    const float* hr = hb + row * HB_PITCH;
    #pragma unroll 4
    for (int k = 0; k < 128; ++k) {
        float a = hr[k];
        const float2* w2 = (const float2*)(Ws2 + k * 40 + c0);
        #pragma unroll
        for (int q = 0; q < 10; ++q) {
            float2 w = w2[q];
            acc2[2 * q]     += a * w.x;
            acc2[2 * q + 1] += a * w.y;
        }
    }

    float m = acc2[0];
    #pragma unroll
    for (int c = 1; c < 20; ++c) m = fmaxf(m, acc2[c]);
    exm[half * 128 + row] = m;
    __syncthreads();
    m = fmaxf(exm[row], exm[128 + row]);

    float s = 0.f;
    #pragma unroll
    for (int c = 0; c < 20; ++c) s += __expf(acc2[c] - m);
    exs[half * 128 + row] = s;
    __syncthreads();
    s = exs[row] + exs[128 + row];
    float ls = m + __logf(s);

    int grow = row0 + row;
    if (grow < n) {
        float4* o4 = (float4*)(out + (size_t)grow * 40 + c0);
        #pragma unroll
        for (int q = 0; q < 5; ++q) {
            float4 o;
            o.x = acc2[q * 4 + 0] - ls;
            o.y = acc2[q * 4 + 1] - ls;
            o.z = acc2[q * 4 + 2] - ls;
            o.w = acc2[q * 4 + 3] - ls;
            o4[q] = o;
        }
    }
}

// ---------------- aggregation: bufA[c] = relu(sc[c]*(bufB[c]+sum bufB[src]) + bc) --------
__global__ void k_agg(const float* __restrict__ bc, int n)
{
    int w = (blockIdx.x * blockDim.x + threadIdx.x) >> 5;
    int lane = threadIdx.x & 31;
    if (w >= n) return;
    const float4* g = (const float4*)d_bufB;
    float4 s = g[w * 32 + lane];   // self-loop term
    int beg = d_rs[w], end = d_rs[w + 1];
    for (int e = beg; e < end; ++e) {
        int src = d_csr[e];
        float4 v = g[src * 32 + lane];
        s.x += v.x; s.y += v.y; s.z += v.z; s.w += v.w;
    }
    float kf = d_sc[w];
    float bx = bc[lane * 4 + 0], by = bc[lane * 4 + 1];
    float bz = bc[lane * 4 + 2], bw = bc[lane * 4 + 3];
    float4 o;
    o.x = fmaxf(kf * s.x + bx, 0.f);
    o.y = fmaxf(kf * s.y + by, 0.f);
    o.z = fmaxf(kf * s.z + bz, 0.f);
    o.w = fmaxf(kf * s.w + bw, 0.f);
    ((float4*)d_bufA)[w * 32 + lane] = o;
}

// ---------------- launch ----------------
extern "C" void kernel_launch(void* const* d_in, const int* in_sizes, int n_in,
                              void* d_out, int out_size)
{
    const float* x    = (const float*)d_in[0];
    const int*   ei   = (const int*)d_in[1];     // int32 (JAX x64 disabled)
    const float* imp  = (const float*)d_in[2];
    const float* W1   = (const float*)d_in[3];
    const float* bl1  = (const float*)d_in[4];
    const float* bc1  = (const float*)d_in[5];
    const float* W2   = (const float*)d_in[6];
    const float* bl2  = (const float*)d_in[7];
    const float* bc2  = (const float*)d_in[8];
    const float* W3   = (const float*)d_in[9];
    const float* bl3  = (const float*)d_in[10];
    const float* bc3  = (const float*)d_in[11];
    const float* Wl1  = (const float*)d_in[12];
    const float* bli1 = (const float*)d_in[13];
    const float* Wl2  = (const float*)d_in[14];
    const float* bli2 = (const float*)d_in[15];
    int n = in_sizes[0] / HF;
    int e = in_sizes[1] / 2;
    float* out = (float*)d_out;

    cudaFuncSetAttribute(k_gemm, cudaFuncAttributeMaxDynamicSharedMemorySize, GEMM_SMEM);

    // preprocessing: CSR build + degree scaling + W images
    k_hist   <<<(e + 255) / 256, 256>>>(ei + e, e, n);
    int nb = (n + 1023) / 1024;
    k_scan1  <<<nb, 1024>>>(n);
    k_scan2  <<<1, 32>>>(nb);
    k_scan3  <<<(n + 255) / 256, 256>>>(n);
    k_scatter<<<(e + 255) / 256, 256>>>(ei, e, n);
    k_prepw  <<<4, 256>>>(W1, W2, W3, Wl1, imp);

    int gblocks = (n + 127) / 128;
    int ablocks = (n + 7) / 8;

    // conv1: A = x (imp folded into image 0); dinv rowscale in epilogue -> bufB
    k_gemm<<<gblocks, 256, GEMM_SMEM>>>(x, bl1, 0, 1, 0,
                                        0, nullptr, nullptr, nullptr, n);
    k_agg <<<ablocks, 256>>>(bc1, n);
    // conv2
    k_gemm<<<gblocks, 256, GEMM_SMEM>>>(nullptr, bl2, 1, 1, 0,
                                        0, nullptr, nullptr, nullptr, n);
    k_agg <<<ablocks, 256>>>(bc2, n);
    // conv3
    k_gemm<<<gblocks, 256, GEMM_SMEM>>>(nullptr, bl3, 2, 1, 0,
                                        0, nullptr, nullptr, nullptr, n);
    k_agg <<<ablocks, 256>>>(bc3, n);
    // lin1 + relu, fused lin2 + log_softmax -> out
    k_gemm<<<gblocks, 256, GEMM_SMEM>>>(nullptr, bli1, 3, 0, 1,
                                        1, Wl2, bli2, out, n);
}

// round 13
// speedup vs baseline: 1.1896x; 1.0074x over previous
#include <cuda_runtime.h>
#include <cstdint>

#define N_MAX 100000
#define E_MAX 600000
#define HF 128

// ---------------- scratch (static __device__ — no allocation) ----------------
__device__ __align__(16) float d_bufA[N_MAX * HF];
__device__ __align__(16) float d_bufB[N_MAX * HF];
__device__ int   d_cnt[N_MAX];
__device__ int   d_incl[N_MAX];
__device__ int   d_rs[N_MAX + 1];
__device__ int   d_cursor[N_MAX];
__device__ int   d_csr[E_MAX];
__device__ float d_dinv[N_MAX];
__device__ float d_sc[N_MAX];     // dinv/deg
__device__ int   d_bsum[256];
__device__ int   d_bpref[256];
// k-major W images: d_wimgT[l][k*128 + j] = W_l[j][k] (* imp[k] for l==0)
__device__ __align__(16) float d_wimgT[4][16384];

// ---------------- preprocessing: CSR-by-target + degree terms ----------------
__global__ void k_hist(const int* __restrict__ col, int e, int n) {
    int i = blockIdx.x * blockDim.x + threadIdx.x;
    if (i < e) {
        int c = col[i];
        if (c >= 0 && c < n) atomicAdd(&d_cnt[c], 1);
    }
}

__global__ void k_scan1(int n) {
    __shared__ int s[1024];
    int t = threadIdx.x;
    int i = blockIdx.x * 1024 + t;
    s[t] = (i < n) ? d_cnt[i] : 0;
    __syncthreads();
    for (int off = 1; off < 1024; off <<= 1) {
        int a = 0;
        if (t >= off) a = s[t - off];
        __syncthreads();
        s[t] += a;
        __syncthreads();
    }
    if (i < n) d_incl[i] = s[t];
    if (t == 1023) d_bsum[blockIdx.x] = s[1023];
}

__global__ void k_scan2(int nb) {   // single warp, shfl scan with carry
    int lane = threadIdx.x;
    int carry = 0;
    for (int base = 0; base < nb; base += 32) {
        int i = base + lane;
        int own = (i < nb) ? d_bsum[i] : 0;
        int v = own;
        #pragma unroll
        for (int o = 1; o < 32; o <<= 1) {
            int t = __shfl_up_sync(0xffffffffu, v, o);
            if (lane >= o) v += t;
        }
        if (i < nb) d_bpref[i] = carry + v - own;   // exclusive
        carry += __shfl_sync(0xffffffffu, v, 31);
    }
}

__global__ void k_scan3(int n) {
    int i = blockIdx.x * blockDim.x + threadIdx.x;
    if (i >= n) return;
    int gi = d_incl[i] + d_bpref[i >> 10];
    int c  = d_cnt[i];
    d_cnt[i] = 0;                        // re-zero for next graph replay
    int st = gi - c;
    d_rs[i] = st;
    d_cursor[i] = st;
    if (i == n - 1) d_rs[n] = gi;
    float deg = (float)(c + 1);          // degree incl. self-loop
    float di = rsqrtf(deg);
    d_dinv[i] = di;
    d_sc[i]   = di / deg;
}

__global__ void k_scatter(const int* __restrict__ ei, int e, int n) {
    int i = blockIdx.x * blockDim.x + threadIdx.x;
    if (i >= e) return;
    int c = ei[e + i];  // col (target)
    int r = ei[i];      // row (source)
    if (c < 0 || c >= n || r < 0 || r >= n) return;
    int pos = atomicAdd(&d_cursor[c], 1);
    d_csr[pos] = r;
}

// ---------------- W prep: k-major transpose (imp folded into layer 0) ----------------
__global__ void __launch_bounds__(256) k_prepw(
    const float* __restrict__ Wa, const float* __restrict__ Wb,
    const float* __restrict__ Wc, const float* __restrict__ Wd,
    const float* __restrict__ imp)
{
    int l = blockIdx.x;
    const float* W = (l == 0) ? Wa : (l == 1) ? Wb : (l == 2) ? Wc : Wd;
    for (int idx = threadIdx.x; idx < 16384; idx += 256) {
        int k = idx >> 7, j = idx & 127;
        float v = W[j * 128 + k];
        if (l == 0) v *= imp[k];
        d_wimgT[l][idx] = v;
    }
}

// ================= shared GEMM machinery =================
// 128x128 tile, 256 threads, 8x8 microtile (rows {4ty+i, +64}, cols {4tx+j, +64}).
// Bs: k-major, 16B-chunk XOR swizzle (chunk ^ (k&31)): fill & loads conflict-free.
// As: k-major [2][32][128], register-staged LDG prefetch + transpose scatter.
#define OFF_AS   65536
#define ASTAGE4  1024                       // float4s per stage
#define GEMM_SMEM (65536 + 32768)           // 98304 B
// fused-lin2 epilogue layout (reuses all smem):
#define HB_PITCH 133
#define OFF_WS2  68096
#define OFF_EXM  88576
#define OFF_EXS  89600

#define SCATTER_A(dstp) do { \
    int kb = lh * 16; \
    (dstp)[(kb + 0) * 128 + lr] = nxt0.x;  (dstp)[(kb + 1) * 128 + lr] = nxt0.y; \
    (dstp)[(kb + 2) * 128 + lr] = nxt0.z;  (dstp)[(kb + 3) * 128 + lr] = nxt0.w; \
    (dstp)[(kb + 4) * 128 + lr] = nxt1.x;  (dstp)[(kb + 5) * 128 + lr] = nxt1.y; \
    (dstp)[(kb + 6) * 128 + lr] = nxt1.z;  (dstp)[(kb + 7) * 128 + lr] = nxt1.w; \
    (dstp)[(kb + 8) * 128 + lr] = nxt2.x;  (dstp)[(kb + 9) * 128 + lr] = nxt2.y; \
    (dstp)[(kb +10) * 128 + lr] = nxt2.z;  (dstp)[(kb +11) * 128 + lr] = nxt2.w; \
    (dstp)[(kb +12) * 128 + lr] = nxt3.x;  (dstp)[(kb +13) * 128 + lr] = nxt3.y; \
    (dstp)[(kb +14) * 128 + lr] = nxt3.z;  (dstp)[(kb +15) * 128 + lr] = nxt3.w; \
} while (0)

#define LOAD_A_CHUNK(kc_) do { \
    nxt0 = nxt1 = nxt2 = nxt3 = make_float4(0.f, 0.f, 0.f, 0.f); \
    if (lgr < n) { \
        size_t b = (size_t)lgr * 32 + (kc_) * 8 + lh * 4; \
        nxt0 = S4[b + 0]; nxt1 = S4[b + 1]; nxt2 = S4[b + 2]; nxt3 = S4[b + 3]; \
    } \
} while (0)

#define FILL_BS() do { \
    const float4* wT4 = (const float4*)wT; \
    _Pragma("unroll") \
    for (int it = 0; it < 16; ++it) { \
        int idx = tid + it * 256; \
        int k = idx >> 5, j4 = idx & 31; \
        Bs4[k * 32 + (j4 ^ (k & 31))] = wT4[idx]; \
    } \
} while (0)

#define COMPUTE_CHUNK(kc_) do { \
    const float4* A4s = (const float4*)(Asf + ((kc_) & 1) * (ASTAGE4 * 4)); \
    int kbase = (kc_) * 32; \
    _Pragma("unroll 8") \
    for (int kl = 0; kl < 32; ++kl) { \
        float4 a0 = A4s[kl * 32 + ty]; \
        float4 a1 = A4s[kl * 32 + ty + 16]; \
        float4 b0 = Bs4[(kbase + kl) * 32 + (tx ^ kl)]; \
        float4 b1 = Bs4[(kbase + kl) * 32 + ((tx + 16) ^ kl)]; \
        float av[8] = {a0.x, a0.y, a0.z, a0.w, a1.x, a1.y, a1.z, a1.w}; \
        float bv[8] = {b0.x, b0.y, b0.z, b0.w, b1.x, b1.y, b1.z, b1.w}; \
        _Pragma("unroll") \
        for (int ii = 0; ii < 8; ii++) \
            _Pragma("unroll") \
            for (int jj = 0; jj < 8; jj++) \
                acc[ii][jj] += av[ii] * bv[jj]; \
    } \
} while (0)

// ---------------- persistent GEMM (layers 1-3): Bs filled once per CTA ----------------
__global__ void __launch_bounds__(256, 2) k_gemmp(
    const float* __restrict__ Aext,       // nullptr -> d_bufA
    const float* __restrict__ bias,
    int wsel, int use_dinv, int relu,
    int n, int ntiles)
{
    extern __shared__ __align__(16) char sm[];
    float4* Bs4 = (float4*)sm;
    float*  Asf = (float*)(sm + OFF_AS);
    int tid = threadIdx.x;
    int tx = tid & 15, ty = tid >> 4;
    const float* A = Aext ? Aext : d_bufA;
    const float4* S4 = (const float4*)A;
    const float* wT = d_wimgT[wsel];
    int lr = tid >> 1, lh = tid & 1;

    FILL_BS();

    float4 nxt0, nxt1, nxt2, nxt3;
    for (int t = blockIdx.x; t < ntiles; t += gridDim.x) {
        int row0 = t * 128;
        int lgr = row0 + lr;

        LOAD_A_CHUNK(0);
        SCATTER_A(Asf);
        __syncthreads();

        float acc[8][8];
        #pragma unroll
        for (int i = 0; i < 8; i++)
            #pragma unroll
            for (int j = 0; j < 8; j++) acc[i][j] = 0.f;

        #pragma unroll
        for (int kc = 0; kc < 4; ++kc) {
            if (kc < 3) LOAD_A_CHUNK(kc + 1);
            COMPUTE_CHUNK(kc);
            if (kc < 3) {
                float* dst = Asf + ((kc + 1) & 1) * (ASTAGE4 * 4);
                SCATTER_A(dst);
                __syncthreads();
            }
        }

        // epilogue -> d_bufB
        #pragma unroll
        for (int ii = 0; ii < 8; ii++) {
            int gr = row0 + ty * 4 + (ii & 3) + (ii >> 2) * 64;
            if (gr >= n) continue;
            float rs = use_dinv ? d_dinv[gr] : 1.f;
            #pragma unroll
            for (int g = 0; g < 2; ++g) {
                int c0 = tx * 4 + g * 64;
                float4 o;
                o.x = (acc[ii][g * 4 + 0] + bias[c0 + 0]) * rs;
                o.y = (acc[ii][g * 4 + 1] + bias[c0 + 1]) * rs;
                o.z = (acc[ii][g * 4 + 2] + bias[c0 + 2]) * rs;
                o.w = (acc[ii][g * 4 + 3] + bias[c0 + 3]) * rs;
                if (relu) {
                    o.x = fmaxf(o.x, 0.f); o.y = fmaxf(o.y, 0.f);
                    o.z = fmaxf(o.z, 0.f); o.w = fmaxf(o.w, 0.f);
                }
                *(float4*)(d_bufB + (size_t)gr * 128 + c0) = o;
            }
        }
        // next tile's chunk-0 store targets stage 0, last read before the
        // kc=2->3 sync; no extra sync needed here beyond the loop-top one.
    }
}

// ---------------- last layer: lin1 + relu, fused lin2 + log_softmax ----------------
__global__ void __launch_bounds__(256, 2) k_gemml(
    const float* __restrict__ bias,       // bli1
    int wsel,
    const float* __restrict__ Wl2,        // [40][128]
    const float* __restrict__ bl2,        // [40]
    float* __restrict__ out,              // [n][40]
    int n)
{
    extern __shared__ __align__(16) char sm[];
    float4* Bs4 = (float4*)sm;
    float*  Asf = (float*)(sm + OFF_AS);
    int tid = threadIdx.x;
    int tx = tid & 15, ty = tid >> 4;
    int row0 = blockIdx.x * 128;
    const float4* S4 = (const float4*)d_bufA;
    const float* wT = d_wimgT[wsel];
    int lr = tid >> 1, lh = tid & 1;
    int lgr = row0 + lr;

    float4 nxt0, nxt1, nxt2, nxt3;
    LOAD_A_CHUNK(0);
    FILL_BS();
    SCATTER_A(Asf);
    __syncthreads();

    float acc[8][8];
    #pragma unroll
    for (int i = 0; i < 8; i++)
        #pragma unroll
        for (int j = 0; j < 8; j++) acc[i][j] = 0.f;

    #pragma unroll
    for (int kc = 0; kc < 4; ++kc) {
        if (kc < 3) LOAD_A_CHUNK(kc + 1);
        COMPUTE_CHUNK(kc);
        if (kc < 3) {
            float* dst = Asf + ((kc + 1) & 1) * (ASTAGE4 * 4);
            SCATTER_A(dst);
            __syncthreads();
        }
    }

    // ---- fused lin2 + log_softmax (h = relu(acc + bias)) ----
    __syncthreads();                        // all smem dead; reuse
    float* hb  = (float*)sm;                // [128][HB_PITCH]
    float* Ws2 = (float*)(sm + OFF_WS2);    // Ws2[k*40 + c] = Wl2[c*128 + k]
    float* exm = (float*)(sm + OFF_EXM);
    float* exs = (float*)(sm + OFF_EXS);

    #pragma unroll
    for (int ii = 0; ii < 8; ii++) {
        int r = ty * 4 + (ii & 3) + (ii >> 2) * 64;
        #pragma unroll
        for (int g = 0; g < 2; ++g) {
            int c0 = tx * 4 + g * 64;
            hb[r * HB_PITCH + c0 + 0] = fmaxf(acc[ii][g * 4 + 0] + bias[c0 + 0], 0.f);
            hb[r * HB_PITCH + c0 + 1] = fmaxf(acc[ii][g * 4 + 1] + bias[c0 + 1], 0.f);
            hb[r * HB_PITCH + c0 + 2] = fmaxf(acc[ii][g * 4 + 2] + bias[c0 + 2], 0.f);
            hb[r * HB_PITCH + c0 + 3] = fmaxf(acc[ii][g * 4 + 3] + bias[c0 + 3], 0.f);
        }
    }
    for (int idx = tid; idx < 5120; idx += 256) {
        int c = idx >> 7, k = idx & 127;
        Ws2[k * 40 + c] = Wl2[idx];
    }
    __syncthreads();

    int row = tid & 127;
    int half = tid >> 7;
    int c0 = half * 20;

    float acc2[20];
    #pragma unroll
    for (int c = 0; c < 20; ++c) acc2[c] = bl2[c0 + c];

    const float* hr = hb + row * HB_PITCH;
    #pragma unroll 4
    for (int k = 0; k < 128; ++k) {
        float a = hr[k];
        const float2* w2 = (const float2*)(Ws2 + k * 40 + c0);
        #pragma unroll
        for (int q = 0; q < 10; ++q) {
            float2 w = w2[q];
            acc2[2 * q]     += a * w.x;
            acc2[2 * q + 1] += a * w.y;
        }
    }

    float m = acc2[0];
    #pragma unroll
    for (int c = 1; c < 20; ++c) m = fmaxf(m, acc2[c]);
    exm[half * 128 + row] = m;
    __syncthreads();
    m = fmaxf(exm[row], exm[128 + row]);

    float s = 0.f;
    #pragma unroll
    for (int c = 0; c < 20; ++c) s += __expf(acc2[c] - m);
    exs[half * 128 + row] = s;
    __syncthreads();
    s = exs[row] + exs[128 + row];
    float ls = m + __logf(s);

    int grow = row0 + row;
    if (grow < n) {
        float4* o4 = (float4*)(out + (size_t)grow * 40 + c0);
        #pragma unroll
        for (int q = 0; q < 5; ++q) {
            float4 o;
            o.x = acc2[q * 4 + 0] - ls;
            o.y = acc2[q * 4 + 1] - ls;
            o.z = acc2[q * 4 + 2] - ls;
            o.w = acc2[q * 4 + 3] - ls;
            o4[q] = o;
        }
    }
}

// ---------------- aggregation: bufA[c] = relu(sc[c]*(bufB[c]+sum bufB[src]) + bc) --------
__global__ void k_agg(const float* __restrict__ bc, int n)
{
    int w = (blockIdx.x * blockDim.x + threadIdx.x) >> 5;
    int lane = threadIdx.x & 31;
    if (w >= n) return;
    const float4* g = (const float4*)d_bufB;
    float4 s = g[w * 32 + lane];   // self-loop term
    int beg = d_rs[w], end = d_rs[w + 1];
    for (int e = beg; e < end; ++e) {
        int src = d_csr[e];
        float4 v = g[src * 32 + lane];
        s.x += v.x; s.y += v.y; s.z += v.z; s.w += v.w;
    }
    float kf = d_sc[w];
    float bx = bc[lane * 4 + 0], by = bc[lane * 4 + 1];
    float bz = bc[lane * 4 + 2], bw = bc[lane * 4 + 3];
    float4 o;
    o.x = fmaxf(kf * s.x + bx, 0.f);
    o.y = fmaxf(kf * s.y + by, 0.f);
    o.z = fmaxf(kf * s.z + bz, 0.f);
    o.w = fmaxf(kf * s.w + bw, 0.f);
    ((float4*)d_bufA)[w * 32 + lane] = o;
}

// ---------------- launch ----------------
extern "C" void kernel_launch(void* const* d_in, const int* in_sizes, int n_in,
                              void* d_out, int out_size)
{
    const float* x    = (const float*)d_in[0];
    const int*   ei   = (const int*)d_in[1];     // int32 (JAX x64 disabled)
    const float* imp  = (const float*)d_in[2];
    const float* W1   = (const float*)d_in[3];
    const float* bl1  = (const float*)d_in[4];
    const float* bc1  = (const float*)d_in[5];
    const float* W2   = (const float*)d_in[6];
    const float* bl2  = (const float*)d_in[7];
    const float* bc2  = (const float*)d_in[8];
    const float* W3   = (const float*)d_in[9];
    const float* bl3  = (const float*)d_in[10];
    const float* bc3  = (const float*)d_in[11];
    const float* Wl1  = (const float*)d_in[12];
    const float* bli1 = (const float*)d_in[13];
    const float* Wl2  = (const float*)d_in[14];
    const float* bli2 = (const float*)d_in[15];
    int n = in_sizes[0] / HF;
    int e = in_sizes[1] / 2;
    float* out = (float*)d_out;

    cudaFuncSetAttribute(k_gemmp, cudaFuncAttributeMaxDynamicSharedMemorySize, GEMM_SMEM);
    cudaFuncSetAttribute(k_gemml, cudaFuncAttributeMaxDynamicSharedMemorySize, GEMM_SMEM);

    // preprocessing: CSR build + degree scaling + W images
    k_hist   <<<(e + 255) / 256, 256>>>(ei + e, e, n);
    int nb = (n + 1023) / 1024;
    k_scan1  <<<nb, 1024>>>(n);
    k_scan2  <<<1, 32>>>(nb);
    k_scan3  <<<(n + 255) / 256, 256>>>(n);
    k_scatter<<<(e + 255) / 256, 256>>>(ei, e, n);
    k_prepw  <<<4, 256>>>(W1, W2, W3, Wl1, imp);

    int ntiles = (n + 127) / 128;
    int pgrid = ntiles < 296 ? ntiles : 296;    // 2 CTAs/SM persistent
    int ablocks = (n + 7) / 8;

    // conv1: A = x (imp folded into image 0); dinv rowscale in epilogue -> bufB
    k_gemmp<<<pgrid, 256, GEMM_SMEM>>>(x, bl1, 0, 1, 0, n, ntiles);
    k_agg  <<<ablocks, 256>>>(bc1, n);
    // conv2
    k_gemmp<<<pgrid, 256, GEMM_SMEM>>>(nullptr, bl2, 1, 1, 0, n, ntiles);
    k_agg  <<<ablocks, 256>>>(bc2, n);
    // conv3
    k_gemmp<<<pgrid, 256, GEMM_SMEM>>>(nullptr, bl3, 2, 1, 0, n, ntiles);
    k_agg  <<<ablocks, 256>>>(bc3, n);
    // lin1 + relu, fused lin2 + log_softmax -> out
    k_gemml<<<ntiles, 256, GEMM_SMEM>>>(bli1, 3, Wl2, bli2, out, n);
}